// round 13
// baseline (speedup 1.0000x reference)
#include <cuda_runtime.h>
#include <cstdint>
#include <cstddef>

// Adaptive separable convolution (SepConv), sm_103a.
// out[b,c,y,w] = sum_i sum_j inp[b,c,y+i,w+j] * V[b,i,y,w] * Hz[b,j,y,w]
//
// Round-13 = R12 with the shared loads RATE-MATCHED into the FFMA2 stream:
//  * comp_load(qsrc -> compute row i) issues ONE LDS.128 of row i+1 into qdst
//    after every 8 FFMA2s (1 LDS / ~16 issue cyc < crossbar service rate of
//    1 LDS.128 / 4 cyc) -- the L1tex wavefront queue never builds, so the
//    effective LDS latency stays ~30-60cyc and is covered by the comp block.
//    (R3-R12 issued 5 LDS.128 per row as a burst; ~10 warps/SM bursting in
//    phase queued ~200 wavefronts -> ~200cyc effective latency -> the ~35%
//    issue plateau.)
//  * everything else identical to R12: FFMA2 packed math, 4 px/thread,
//    1 channel/CTA, TILE 128x4, 3 CTAs/SM, 3 phases (10/10/8 pairs),
//    ping-pong qA/qB, depth-4 V register ring, packed o accumulators.

#define KF   51
#define BB   2
#define CC   3
#define HH   256
#define WW   256
#define HW   (HH * WW)            // 65536
#define IN_H (HH + KF - 1)        // 306
#define IN_W (WW + KF - 1)        // 306

#define TILE_W 128
#define TILE_H 4
#define PATCH_H (TILE_H + KF - 1) // 54
#define PATCH_W (TILE_W + KF - 1) // 178
#define PATCH_WP 180              // padded row: 720B; cols 178,179 zeroed
#define ROW_BYTES (PATCH_WP * 4)  // 720

#define NTHREADS 128              // 4 warps, one output row each

__device__ __forceinline__ uint64_t pk2(float lo, float hi) {
    uint64_t r;
    asm("mov.b64 %0, {%1,%2};" : "=l"(r) : "f"(lo), "f"(hi));
    return r;
}
__device__ __forceinline__ void ffma2(uint64_t& acc, uint64_t a, uint64_t b) {
    asm("fma.rn.f32x2 %0, %1, %2, %0;" : "+l"(acc) : "l"(a), "l"(b));
}
__device__ __forceinline__ float hadd2(uint64_t p) {
    float lo, hi;
    asm("mov.b64 {%0,%1}, %2;" : "=f"(lo), "=f"(hi) : "l"(p));
    return lo + hi;
}
__device__ __forceinline__ void lds128(uint64_t& q0, uint64_t& q1, uint32_t saddr) {
    asm("ld.shared.v2.u64 {%0,%1}, [%2];" : "=l"(q0), "=l"(q1) : "r"(saddr));
}

// One phase: tap-pairs m = MBASE .. MBASE+NP-1 (NP even, 8*MBASE % 16 == 0).
// Accumulates into packed o0..o3 carried across phases.
template<int MBASE, int NP>
__device__ __forceinline__ void run_phase(
    const float* __restrict__ Hb, const float* __restrict__ Vb,
    uint32_t smbase,
    uint64_t& o0, uint64_t& o1, uint64_t& o2, uint64_t& o3)
{
    // packed weights: w[p][r] = (Hz[2m-p], Hz[2m+1-p]), m = MBASE + r.
    uint64_t w[4][NP];
#pragma unroll
    for (int p = 0; p < 4; ++p) {
#pragma unroll
        for (int r = 0; r < NP; ++r) {
            int m  = MBASE + r;
            int j0 = 2 * m - p;
            int j1 = j0 + 1;
            float f0 = (j0 >= 0 && j0 < KF) ? Hb[(size_t)j0 * HW + p] : 0.0f;
            float f1 = (j1 >= 0 && j1 < KF) ? Hb[(size_t)j1 * HW + p] : 0.0f;
            w[p][r] = pk2(f0, f1);
        }
    }

    const uint32_t sbase = smbase + (uint32_t)(8 * MBASE);
    uint64_t qA[NP], qB[NP];

    auto ldq = [&](uint64_t (&q)[NP], int row) {       // prologue only (burst)
        uint32_t a = sbase + (uint32_t)row * ROW_BYTES;
#pragma unroll
        for (int t = 0; t < NP / 2; ++t)
            lds128(q[2 * t], q[2 * t + 1], a + 16u * t);
    };
    auto ldv = [&](int row) -> float4 {
        return *(const float4*)(Vb + (size_t)row * HW);
    };

    // compute one row from qs while loading ldrow into qd, INTERLEAVED:
    // one LDS.128 after every 8 FFMA2 -> demand rate below crossbar service.
    auto comp_load = [&](const uint64_t (&qs)[NP], uint64_t (&qd)[NP],
                         int ldrow, float4 v) {
        const uint32_t a = sbase + (uint32_t)ldrow * ROW_BYTES;
        uint64_t a0 = 0, a1 = 0, a2 = 0, a3 = 0;
#pragma unroll
        for (int r = 0; r < NP; ++r) {
            ffma2(a0, w[0][r], qs[r]);
            ffma2(a1, w[1][r], qs[r]);
            ffma2(a2, w[2][r], qs[r]);
            ffma2(a3, w[3][r], qs[r]);
            if ((r & 1) == 0)
                lds128(qd[r], qd[r + 1], a + 8u * r);
        }
        ffma2(o0, pk2(v.x, v.x), a0);
        ffma2(o1, pk2(v.y, v.y), a1);
        ffma2(o2, pk2(v.z, v.z), a2);
        ffma2(o3, pk2(v.w, v.w), a3);
    };
    auto comp = [&](const uint64_t (&qs)[NP], float4 v) {   // epilogue row
        uint64_t a0 = 0, a1 = 0, a2 = 0, a3 = 0;
#pragma unroll
        for (int r = 0; r < NP; ++r) {
            ffma2(a0, w[0][r], qs[r]);
            ffma2(a1, w[1][r], qs[r]);
            ffma2(a2, w[2][r], qs[r]);
            ffma2(a3, w[3][r], qs[r]);
        }
        ffma2(o0, pk2(v.x, v.x), a0);
        ffma2(o1, pk2(v.y, v.y), a1);
        ffma2(o2, pk2(v.z, v.z), a2);
        ffma2(o3, pk2(v.w, v.w), a3);
    };

    // prologue: LDS row 0 (burst, once), V rows 0..3 (depth-4 register ring)
    ldq(qA, 0);
    float4 v0 = ldv(0), v1 = ldv(1), v2 = ldv(2), v3 = ldv(3);

    // steady state: 4 rows per iteration, rows 0..47; load rows i+1..i+4
#pragma unroll 1
    for (int i = 0; i < 48; i += 4) {
        comp_load(qA, qB, i + 1, v0); v0 = ldv(i + 4);
        comp_load(qB, qA, i + 2, v1); v1 = ldv(i + 5);
        comp_load(qA, qB, i + 3, v2); v2 = ldv(i + 6);
        comp_load(qB, qA, i + 4, v3); v3 = ldv(i + 7 < KF ? i + 7 : KF - 1);
    }
    // epilogue: rows 48, 49, 50 (qA holds 48; v0,v1,v2 = rows 48,49,50)
    comp_load(qA, qB, 49, v0);
    comp_load(qB, qA, 50, v1);
    comp(qA, v2);
}

__global__ void __launch_bounds__(NTHREADS, 3)
sepconv_kernel(const float* __restrict__ inp,
               const float* __restrict__ ver,
               const float* __restrict__ hor,
               float* __restrict__ out)
{
    __shared__ __align__(16) float sm[PATCH_H][PATCH_WP];

    const int bx = blockIdx.x;            // 0..1   tile col
    const int by = blockIdx.y;            // 0..63  tile row
    const int bc = blockIdx.z;            // 0..5   (b, c) fused
    const int b  = bc / CC;
    const int c  = bc - b * CC;
    const int x0 = bx * TILE_W;
    const int y0 = by * TILE_H;

    const int tid  = threadIdx.x;
    const int lane = tid & 31;
    const int wy   = tid >> 5;            // warp id == row within tile
    const int y    = y0 + wy;             // output row
    const int w0   = x0 + 4 * lane;       // first of 4 output cols

    const float* Hb = hor + ((size_t)b * KF * HW) + (size_t)y * WW + w0;
    const float* Vb = ver + ((size_t)b * KF * HW) + (size_t)y * WW + w0;

    // ---- single patch fill for this CTA's channel (+ zero pad cols) ----
    {
        const float* src = inp + ((size_t)(b * CC + c) * IN_H + y0) * IN_W + x0;
        for (int t = tid; t < PATCH_H * (PATCH_W / 2); t += NTHREADS) {
            int r  = t / (PATCH_W / 2);
            int c2 = t - r * (PATCH_W / 2);
            float2 v = *(const float2*)(src + (size_t)r * IN_W + 2 * c2);
            *(float2*)(&sm[r][2 * c2]) = v;
        }
        if (tid < PATCH_H) {              // pad cols read by the dead pair m=27
            sm[tid][PATCH_W]     = 0.0f;
            sm[tid][PATCH_W + 1] = 0.0f;
        }
    }
    __syncthreads();

    // per-thread shared base address: row wy (+i), float col 4*lane
    const uint32_t smbase = (uint32_t)__cvta_generic_to_shared(&sm[0][0])
                          + (uint32_t)(wy * ROW_BYTES) + (uint32_t)(lane * 16);

    // packed accumulators, carried across all 3 phases
    uint64_t o0 = 0, o1 = 0, o2 = 0, o3 = 0;

    // phases: m = 0..9, 10..19, 20..27 (byte bases 0 / 80 / 160)
    run_phase<0,  10>(Hb, Vb, smbase, o0, o1, o2, o3);
    __syncthreads();   // liveness fence: next phase's weights stay below
    run_phase<10, 10>(Hb, Vb, smbase, o0, o1, o2, o3);
    __syncthreads();
    run_phase<20,  8>(Hb, Vb, smbase, o0, o1, o2, o3);

    // ---- write out ----
    float* o = out + ((size_t)(b * CC + c) * HH + y) * WW + w0;
    *(float4*)o = make_float4(hadd2(o0), hadd2(o1), hadd2(o2), hadd2(o3));
}

extern "C" void kernel_launch(void* const* d_in, const int* in_sizes, int n_in,
                              void* d_out, int out_size)
{
    (void)in_sizes; (void)n_in; (void)out_size;
    const float* inp = (const float*)d_in[0];   // [B, C, 306, 306]
    const float* ver = (const float*)d_in[1];   // [B, 51, 256, 256]
    const float* hor = (const float*)d_in[2];   // [B, 51, 256, 256]
    float*       out = (float*)d_out;           // [B, C, 256, 256]

    dim3 grid(WW / TILE_W, HH / TILE_H, BB * CC);   // (2, 64, 6) = 768 blocks
    dim3 block(NTHREADS);
    sepconv_kernel<<<grid, block>>>(inp, ver, hor, out);
}

// round 15
// speedup vs baseline: 1.0004x; 1.0004x over previous
#include <cuda_runtime.h>
#include <cstdint>
#include <cstddef>

// Adaptive separable convolution (SepConv), sm_103a.
// out[b,c,y,w] = sum_i sum_j inp[b,c,y+i,w+j] * V[b,i,y,w] * Hz[b,j,y,w]
//
// Round-15 = Round-14 with the epilogue double-count bug fixed (the loop
// computes TWO rows per iteration -> rows 0..49; epilogue is row 50 only;
// R14 accumulated row 50 twice -> rel_err 0.14).
//
// Design = R3 champion skeleton (2 phases, 4px/thread, TILE 128x4,
// 3 CTAs/SM, burst LDS.128) + accumulated micro-wins:
//  * float4 weight loads: ONE LDG.128 per tap j loads Hz for all 4 pixels
//    (R3 used 4 scalar LDGs/tap -> 4x the L1 wavefronts, ~400 extra instrs).
//    Pairs repacked from a sliding float4 window via register movs.
//  * V register ring depth 2 (validated in R12).
//  * packed o-accumulators carried across both phases (validated R11/12).

#define KF   51
#define BB   2
#define CC   3
#define HH   256
#define WW   256
#define HW   (HH * WW)            // 65536
#define IN_H (HH + KF - 1)        // 306
#define IN_W (WW + KF - 1)        // 306

#define TILE_W 128
#define TILE_H 4
#define PATCH_H (TILE_H + KF - 1) // 54
#define PATCH_W (TILE_W + KF - 1) // 178
#define PATCH_WP 180              // padded row: 720B, 16B-aligned
#define ROW_BYTES (PATCH_WP * 4)  // 720

#define NTHREADS 128              // 4 warps, one output row each

__device__ __forceinline__ uint64_t pk2(float lo, float hi) {
    uint64_t r;
    asm("mov.b64 %0, {%1,%2};" : "=l"(r) : "f"(lo), "f"(hi));
    return r;
}
__device__ __forceinline__ void ffma2(uint64_t& acc, uint64_t a, uint64_t b) {
    asm("fma.rn.f32x2 %0, %1, %2, %0;" : "+l"(acc) : "l"(a), "l"(b));
}
__device__ __forceinline__ float hadd2(uint64_t p) {
    float lo, hi;
    asm("mov.b64 {%0,%1}, %2;" : "=f"(lo), "=f"(hi) : "l"(p));
    return lo + hi;
}
__device__ __forceinline__ void lds128(uint64_t& q0, uint64_t& q1, uint32_t saddr) {
    asm("ld.shared.v2.u64 {%0,%1}, [%2];" : "=l"(q0), "=l"(q1) : "r"(saddr));
}

// Load Hz float4 for tap j (all 4 pixels at once); zero outside [0, KF).
__device__ __forceinline__ float4 ldh4(const float* Hb, int j) {
    if (j >= 0 && j < KF) return *(const float4*)(Hb + (size_t)j * HW);
    return make_float4(0.f, 0.f, 0.f, 0.f);
}

// One phase: tap-pairs k = MBASE .. MBASE+NP-1. Weight pairs built from
// float4 taps: w0[k]=(h[2k].x,h[2k+1].x), w1[k]=(h[2k-1].y,h[2k].y),
// w2[k]=(h[2k-2].z,h[2k-1].z), w3[k]=(h[2k-3].w,h[2k-2].w).
// Accumulates into packed o0..o3 carried across phases.
template<int MBASE, int NP>
__device__ __forceinline__ void run_phase(
    const float* __restrict__ Hb, const float* __restrict__ Vb,
    uint32_t smbase,
    uint64_t& o0, uint64_t& o1, uint64_t& o2, uint64_t& o3)
{
    uint64_t w0[NP], w1[NP], w2[NP], w3[NP];
    {
        // sliding window of float4 taps: need j = 2k-3 .. 2k+1 per pair k
        float4 f_m3 = ldh4(Hb, 2 * MBASE - 3);
        float4 f_m2 = ldh4(Hb, 2 * MBASE - 2);
        float4 f_m1 = ldh4(Hb, 2 * MBASE - 1);
#pragma unroll
        for (int r = 0; r < NP; ++r) {
            int k = MBASE + r;
            float4 f0 = ldh4(Hb, 2 * k);
            float4 f1 = ldh4(Hb, 2 * k + 1);
            w0[r] = pk2(f0.x,   f1.x);
            w1[r] = pk2(f_m1.y, f0.y);
            w2[r] = pk2(f_m2.z, f_m1.z);
            w3[r] = pk2(f_m3.w, f_m2.w);
            f_m3 = f_m1; f_m2 = f0; f_m1 = f1;
        }
    }

    const uint32_t sbase = smbase + (uint32_t)(8 * MBASE);
    uint64_t q[NP];

    auto ldq = [&](int row) {
        uint32_t a = sbase + (uint32_t)row * ROW_BYTES;
#pragma unroll
        for (int t = 0; t < NP / 2; ++t)
            lds128(q[2 * t], q[2 * t + 1], a + 16u * t);
        if (NP & 1)
            asm("ld.shared.b64 %0, [%1];" : "=l"(q[NP - 1])
                : "r"(a + 8u * (NP - 1)));
    };
    auto ldv = [&](int row) -> float4 {
        return *(const float4*)(Vb + (size_t)row * HW);
    };
    auto comp = [&](float4 v) {
        uint64_t a0 = 0, a1 = 0, a2 = 0, a3 = 0;
#pragma unroll
        for (int r = 0; r < NP; ++r) {
            ffma2(a0, w0[r], q[r]);
            ffma2(a1, w1[r], q[r]);
            ffma2(a2, w2[r], q[r]);
            ffma2(a3, w3[r], q[r]);
        }
        ffma2(o0, pk2(v.x, v.x), a0);
        ffma2(o1, pk2(v.y, v.y), a1);
        ffma2(o2, pk2(v.z, v.z), a2);
        ffma2(o3, pk2(v.w, v.w), a3);
    };

    // mainloop: 2 rows per iteration (rows 0..49), depth-2 V ring
    ldq(0);
    float4 va = ldv(0);
    float4 vb = ldv(1);
#pragma unroll 1
    for (int i = 0; i + 2 < KF; i += 2) {      // i = 0,2,...,48
        comp(va);  va = ldv(i + 2);            // row i
        ldq(i + 1);
        comp(vb);  vb = ldv(i + 3 < KF ? i + 3 : KF - 1);   // row i+1
        ldq(i + 2);
    }
    comp(va);      // row 50 (q holds row 50, va = V[50]) -- ONLY epilogue row
}

__global__ void __launch_bounds__(NTHREADS, 3)
sepconv_kernel(const float* __restrict__ inp,
               const float* __restrict__ ver,
               const float* __restrict__ hor,
               float* __restrict__ out)
{
    __shared__ __align__(16) float sm[PATCH_H][PATCH_WP];

    const int bx = blockIdx.x;            // 0..1   tile col
    const int by = blockIdx.y;            // 0..63  tile row
    const int bc = blockIdx.z;            // 0..5   (b, c) fused
    const int b  = bc / CC;
    const int c  = bc - b * CC;
    const int x0 = bx * TILE_W;
    const int y0 = by * TILE_H;

    const int tid  = threadIdx.x;
    const int lane = tid & 31;
    const int wy   = tid >> 5;            // warp id == row within tile
    const int y    = y0 + wy;             // output row
    const int w0   = x0 + 4 * lane;       // first of 4 output cols

    const float* Hb = hor + ((size_t)b * KF * HW) + (size_t)y * WW + w0;
    const float* Vb = ver + ((size_t)b * KF * HW) + (size_t)y * WW + w0;

    // ---- single patch fill for this CTA's channel (+ zero pad cols) ----
    {
        const float* src = inp + ((size_t)(b * CC + c) * IN_H + y0) * IN_W + x0;
        for (int t = tid; t < PATCH_H * (PATCH_W / 2); t += NTHREADS) {
            int r  = t / (PATCH_W / 2);
            int c2 = t - r * (PATCH_W / 2);
            float2 v = *(const float2*)(src + (size_t)r * IN_W + 2 * c2);
            *(float2*)(&sm[r][2 * c2]) = v;
        }
        if (tid < PATCH_H) {              // pad cols read by the dead pair m=27
            sm[tid][PATCH_W]     = 0.0f;
            sm[tid][PATCH_W + 1] = 0.0f;
        }
    }
    __syncthreads();

    // per-thread shared base address: row wy (+i), float col 4*lane
    const uint32_t smbase = (uint32_t)__cvta_generic_to_shared(&sm[0][0])
                          + (uint32_t)(wy * ROW_BYTES) + (uint32_t)(lane * 16);

    // packed accumulators, carried across both phases
    uint64_t o0 = 0, o1 = 0, o2 = 0, o3 = 0;

    // phases: pairs k = 0..13 and 14..27 (byte bases 0 / 112; m=27 pads)
    run_phase<0,  14>(Hb, Vb, smbase, o0, o1, o2, o3);
    __syncthreads();   // liveness fence: phase-B weights stay below phase A
    run_phase<14, 14>(Hb, Vb, smbase, o0, o1, o2, o3);

    // ---- write out ----
    float* o = out + ((size_t)(b * CC + c) * HH + y) * WW + w0;
    *(float4*)o = make_float4(hadd2(o0), hadd2(o1), hadd2(o2), hadd2(o3));
}

extern "C" void kernel_launch(void* const* d_in, const int* in_sizes, int n_in,
                              void* d_out, int out_size)
{
    (void)in_sizes; (void)n_in; (void)out_size;
    const float* inp = (const float*)d_in[0];   // [B, C, 306, 306]
    const float* ver = (const float*)d_in[1];   // [B, 51, 256, 256]
    const float* hor = (const float*)d_in[2];   // [B, 51, 256, 256]
    float*       out = (float*)d_out;           // [B, C, 256, 256]

    dim3 grid(WW / TILE_W, HH / TILE_H, BB * CC);   // (2, 64, 6) = 768 blocks
    dim3 block(NTHREADS);
    sepconv_kernel<<<grid, block>>>(inp, ver, hor, out);
}